// round 2
// baseline (speedup 1.0000x reference)
#include <cuda_runtime.h>

#define NN 4096
#define BB 4
#define C_IN 128
#define C_OUT 64
#define ROWCHUNKS 32

// ---------------- scratch (static device globals; no allocation) -------------
__device__ float g_h   [BB * NN * C_OUT];   // projected features
__device__ float g_h2  [BB * NN * C_OUT];   // h / S (column-softmax denom folded in)
__device__ float g_f1  [BB * NN];           // own-type k score
__device__ float g_f2  [BB * NN];           // own-type v score
__device__ float g_Sp  [ROWCHUNKS * BB * NN]; // partial column sums (deterministic)
__device__ float g_rS  [BB * NN];           // 1 / S

// ---------------- kernel 1: h = node_rep @ proj_W^T + proj_b -----------------
__global__ __launch_bounds__(256) void k_proj(const float* __restrict__ node_rep,
                                              const float* __restrict__ proj_W,
                                              const float* __restrict__ proj_b) {
    __shared__ float pw[C_OUT][C_IN + 1];   // +1 pad: kill 32-way conflict
    __shared__ float nr[16][C_IN];
    int tid = threadIdx.x;
    for (int k = tid; k < C_OUT * C_IN; k += 256)
        pw[k / C_IN][k % C_IN] = proj_W[k];
    int row0 = blockIdx.x * 16;  // rows are flattened (b*N + n)
    for (int k = tid; k < 16 * C_IN; k += 256)
        nr[k / C_IN][k % C_IN] = node_rep[(row0 + k / C_IN) * C_IN + (k % C_IN)];
    __syncthreads();

    int o  = tid & 63;
    int rg = tid >> 6;
    float bias = proj_b[o];
    #pragma unroll
    for (int rr = 0; rr < 4; rr++) {
        int r = rg * 4 + rr;
        float acc = bias;
        #pragma unroll 16
        for (int c = 0; c < C_IN; c++) acc += nr[r][c] * pw[o][c];
        g_h[(row0 + r) * C_OUT + o] = acc;
    }
}

// ---------------- kernel 2: f1/f2 = own-type gate scalars --------------------
__global__ __launch_bounds__(256) void k_scores(const int*   __restrict__ node_type,
                                                const float* __restrict__ k_W,
                                                const float* __restrict__ k_b,
                                                const float* __restrict__ v_W,
                                                const float* __restrict__ v_b) {
    int warp = threadIdx.x >> 5;
    int lane = threadIdx.x & 31;
    int row  = blockIdx.x * 8 + warp;          // 0 .. B*N-1
    int t = node_type[row & (NN - 1)];
    float h0 = g_h[row * 64 + lane];
    float h1 = g_h[row * 64 + lane + 32];
    float p1 = h0 * k_W[t * 64 + lane] + h1 * k_W[t * 64 + lane + 32];
    float p2 = h0 * v_W[t * 64 + lane] + h1 * v_W[t * 64 + lane + 32];
    #pragma unroll
    for (int off = 16; off; off >>= 1) {
        p1 += __shfl_down_sync(0xffffffffu, p1, off);
        p2 += __shfl_down_sync(0xffffffffu, p2, off);
    }
    if (lane == 0) {
        g_f1[row] = p1 + k_b[t];
        g_f2[row] = p2 + v_b[t];
    }
}

__device__ __forceinline__ float e_of(float a, float f1, float f2) {
    float x  = a * (f1 + f2);
    float sg = __fdividef(1.0f, 1.0f + __expf(-x));
    return __expf(sg - 0.5f);
}

// ---------------- kernel 3: partial column sums over row chunks --------------
__global__ __launch_bounds__(128) void k_colsum(const float* __restrict__ adj) {
    int j  = blockIdx.x * 128 + threadIdx.x;
    int rc = blockIdx.y;                         // 0..31
    float f2v[BB], s[BB];
    #pragma unroll
    for (int b = 0; b < BB; b++) { f2v[b] = g_f2[b * NN + j]; s[b] = 0.0f; }
    int i0 = rc * 128;
    for (int ii = 0; ii < 128; ii++) {
        int i = i0 + ii;
        float a = adj[i * NN + j];               // coalesced across threads
        #pragma unroll
        for (int b = 0; b < BB; b++)
            s[b] += e_of(a, g_f1[b * NN + i], f2v[b]);
    }
    #pragma unroll
    for (int b = 0; b < BB; b++)
        g_Sp[(rc * BB + b) * NN + j] = s[b];
}

// ---------------- kernel 4: rS = 1/S ----------------------------------------
__global__ __launch_bounds__(256) void k_reduceS() {
    int idx = blockIdx.x * 256 + threadIdx.x;    // 0 .. B*N-1
    float s = 0.0f;
    #pragma unroll
    for (int rc = 0; rc < ROWCHUNKS; rc++) s += g_Sp[rc * BB * NN + idx];
    g_rS[idx] = __fdividef(1.0f, s);
}

// ---------------- kernel 5: h2 = h * rS (per row) -----------------------------
__global__ __launch_bounds__(256) void k_scaleh() {
    int idx4 = blockIdx.x * 256 + threadIdx.x;   // over B*N*64/4 float4s
    float4 v = ((const float4*)g_h)[idx4];
    float r  = g_rS[idx4 >> 4];
    v.x *= r; v.y *= r; v.z *= r; v.w *= r;
    ((float4*)g_h2)[idx4] = v;
}

// ---------------- kernel 6: out = E @ h2 (E built on the fly) ----------------
#define FMA4(A, s, H) { A.x += (s)*(H).x; A.y += (s)*(H).y; A.z += (s)*(H).z; A.w += (s)*(H).w; }

__global__ __launch_bounds__(256) void k_main(const float* __restrict__ adj,
                                              float* __restrict__ out) {
    __shared__ float Es[64 * 64];   // [i][j], row-major
    __shared__ float Hs[64 * 64];   // [j][o], row-major
    int tid = threadIdx.x;
    int it  = blockIdx.x;           // i-tile 0..63
    int b   = blockIdx.y;           // 0..3
    int i0  = it * 64;

    int ox = tid & 15;              // o-group: o = ox*4 + q
    int iy = tid >> 4;              // i-group: i = iy*4 + r

    float4 acc[4];
    #pragma unroll
    for (int r = 0; r < 4; r++) acc[r] = make_float4(0.f, 0.f, 0.f, 0.f);

    const float4* adj4 = (const float4*)adj;
    const float4* f24  = (const float4*)(g_f2 + b * NN);
    const float4* h24  = (const float4*)(g_h2 + (size_t)b * NN * 64);
    float4* ES4 = (float4*)Es;
    float4* HS4 = (float4*)Hs;

    for (int jc = 0; jc < 64; jc++) {
        int j0 = jc * 64;
        __syncthreads();
        #pragma unroll
        for (int k = 0; k < 4; k++) {
            int idx4 = tid + 256 * k;            // 0..1023
            int i  = idx4 >> 4;                  // 0..63
            int jq = idx4 & 15;                  // float4 column within tile
            float4 a  = adj4[((i0 + i) * NN + j0) / 4 + jq];
            float  f1 = g_f1[b * NN + i0 + i];
            float4 f2 = f24[j0 / 4 + jq];
            float4 e;
            e.x = e_of(a.x, f1, f2.x);
            e.y = e_of(a.y, f1, f2.y);
            e.z = e_of(a.z, f1, f2.z);
            e.w = e_of(a.w, f1, f2.w);
            ES4[i * 16 + jq] = e;                // consecutive tid -> consecutive jq: conflict-free
            HS4[i * 16 + jq] = h24[(j0 + i) * 16 + jq];  // (reuse i as j-row, jq as o-quad)
        }
        __syncthreads();

        #pragma unroll 4
        for (int j = 0; j < 64; j += 4) {
            float4 e0 = ES4[(iy * 4 + 0) * 16 + (j >> 2)];
            float4 e1 = ES4[(iy * 4 + 1) * 16 + (j >> 2)];
            float4 e2 = ES4[(iy * 4 + 2) * 16 + (j >> 2)];
            float4 e3 = ES4[(iy * 4 + 3) * 16 + (j >> 2)];
            float4 h0 = HS4[(j + 0) * 16 + ox];
            float4 h1 = HS4[(j + 1) * 16 + ox];
            float4 h2 = HS4[(j + 2) * 16 + ox];
            float4 h3 = HS4[(j + 3) * 16 + ox];
            FMA4(acc[0], e0.x, h0); FMA4(acc[0], e0.y, h1); FMA4(acc[0], e0.z, h2); FMA4(acc[0], e0.w, h3);
            FMA4(acc[1], e1.x, h0); FMA4(acc[1], e1.y, h1); FMA4(acc[1], e1.z, h2); FMA4(acc[1], e1.w, h3);
            FMA4(acc[2], e2.x, h0); FMA4(acc[2], e2.y, h1); FMA4(acc[2], e2.z, h2); FMA4(acc[2], e2.w, h3);
            FMA4(acc[3], e3.x, h0); FMA4(acc[3], e3.y, h1); FMA4(acc[3], e3.z, h2); FMA4(acc[3], e3.w, h3);
        }
    }

    #pragma unroll
    for (int r = 0; r < 4; r++) {
        int row = b * NN + i0 + iy * 4 + r;
        ((float4*)out)[row * 16 + ox] = acc[r];
    }
}

// ---------------- launch ------------------------------------------------------
extern "C" void kernel_launch(void* const* d_in, const int* in_sizes, int n_in,
                              void* d_out, int out_size) {
    const float* node_rep = (const float*)d_in[0];   // [B,N,128]
    const float* adj      = (const float*)d_in[1];   // [N,N]
    const int*   node_ty  = (const int*)  d_in[2];   // [N]
    const float* proj_W   = (const float*)d_in[3];   // [64,128]
    const float* proj_b   = (const float*)d_in[4];   // [64]
    const float* k_W      = (const float*)d_in[5];   // [5,64]
    const float* k_b      = (const float*)d_in[6];   // [5]
    const float* v_W      = (const float*)d_in[7];   // [5,64]
    const float* v_b      = (const float*)d_in[8];   // [5]
    float* out = (float*)d_out;                      // [B,N,64]

    k_proj   <<<(BB * NN) / 16, 256>>>(node_rep, proj_W, proj_b);
    k_scores <<<(BB * NN) / 8, 256>>>(node_ty, k_W, k_b, v_W, v_b);
    k_colsum <<<dim3(NN / 128, ROWCHUNKS), 128>>>(adj);
    k_reduceS<<<(BB * NN) / 256, 256>>>();
    k_scaleh <<<(BB * NN * C_OUT / 4) / 256, 256>>>();
    k_main   <<<dim3(NN / 64, BB), 256>>>(adj, out);
}